// round 5
// baseline (speedup 1.0000x reference)
#include <cuda_runtime.h>
#include <math.h>

#define H_IMG 256
#define W_IMG 256
#define TILE 8
#define TANFOV 0.7f
#define ALPHA_MIN (1.0f/255.0f)
#define MAXG 512

__device__ float4 g_bbv[MAXG];               // xmin, xmax, ymin, ymax
__device__ float4 g_p1v[MAXG];               // mx, my, conicA, conicB
__device__ float4 g_p2v[MAXG];               // conicC, opacity, z, 0
__device__ float4 g_clv[MAXG];               // r, g, b, 0
__device__ unsigned long long g_keyv[MAXG];  // (float_bits(z)<<32) | idx

__global__ __launch_bounds__(256) void gs_pre(
    const float* __restrict__ means,
    const float* __restrict__ opac,
    const float* __restrict__ colors,
    const float* __restrict__ scales,
    const float* __restrict__ rots,
    const float* __restrict__ vm,
    float* __restrict__ radii_out, int n)
{
    const int i = blockIdx.x * 256 + threadIdx.x;
    if (i >= n) return;

    const float fx = W_IMG / (2.0f * TANFOV);
    const float fy = H_IMG / (2.0f * TANFOV);
    const float R00 = vm[0], R01 = vm[1], R02 = vm[2],  t0 = vm[3];
    const float R10 = vm[4], R11 = vm[5], R12 = vm[6],  t1 = vm[7];
    const float R20 = vm[8], R21 = vm[9], R22 = vm[10], t2 = vm[11];

    float m0 = means[3*i], m1 = means[3*i+1], m2 = means[3*i+2];
    float pxv = R00*m0 + R01*m1 + R02*m2 + t0;
    float pyv = R10*m0 + R11*m1 + R12*m2 + t1;
    float zg  = R20*m0 + R21*m1 + R22*m2 + t2;
    float zc = fmaxf(zg, 1e-4f);
    float lim = 1.3f * TANFOV;
    float txc = fminf(fmaxf(pxv/zc, -lim), lim) * zc;
    float tyc = fminf(fmaxf(pyv/zc, -lim), lim) * zc;

    float q0 = rots[4*i], q1 = rots[4*i+1], q2 = rots[4*i+2], q3 = rots[4*i+3];
    float qn = rsqrtf(q0*q0 + q1*q1 + q2*q2 + q3*q3);
    q0 *= qn; q1 *= qn; q2 *= qn; q3 *= qn;
    float xx = q1*q1, yy = q2*q2, zz = q3*q3;
    float xy = q1*q2, xz = q1*q3, yz = q2*q3;
    float rx = q0*q1, ry = q0*q2, rz = q0*q3;
    float Q00 = 1.f-2.f*(yy+zz), Q01 = 2.f*(xy-rz),     Q02 = 2.f*(xz+ry);
    float Q10 = 2.f*(xy+rz),     Q11 = 1.f-2.f*(xx+zz), Q12 = 2.f*(yz-rx);
    float Q20 = 2.f*(xz-ry),     Q21 = 2.f*(yz+rx),     Q22 = 1.f-2.f*(xx+yy);
    float sx = scales[3*i], sy = scales[3*i+1], sz2 = scales[3*i+2];
    float M00 = Q00*sx, M01 = Q01*sy, M02 = Q02*sz2;
    float M10 = Q10*sx, M11 = Q11*sy, M12 = Q12*sz2;
    float M20 = Q20*sx, M21 = Q21*sy, M22 = Q22*sz2;
    float C00 = M00*M00 + M01*M01 + M02*M02;
    float C01 = M00*M10 + M01*M11 + M02*M12;
    float C02 = M00*M20 + M01*M21 + M02*M22;
    float C11 = M10*M10 + M11*M11 + M12*M12;
    float C12 = M10*M20 + M11*M21 + M12*M22;
    float C22 = M20*M20 + M21*M21 + M22*M22;
    float j00 = fx/zc, j02 = -fx*txc/(zc*zc);
    float j11 = fy/zc, j12 = -fy*tyc/(zc*zc);
    float T00 = j00*R00 + j02*R20, T01 = j00*R01 + j02*R21, T02 = j00*R02 + j02*R22;
    float T10 = j11*R10 + j12*R20, T11 = j11*R11 + j12*R21, T12 = j11*R12 + j12*R22;
    float u0 = C00*T00 + C01*T01 + C02*T02;
    float u1 = C01*T00 + C11*T01 + C12*T02;
    float u2 = C02*T00 + C12*T01 + C22*T02;
    float v0 = C00*T10 + C01*T11 + C02*T12;
    float v1 = C01*T10 + C11*T11 + C12*T12;
    float v2 = C02*T10 + C12*T11 + C22*T12;
    float a  = T00*u0 + T01*u1 + T02*u2 + 0.3f;
    float bq = T10*u0 + T11*u1 + T12*u2;
    float c  = T10*v0 + T11*v1 + T12*v2 + 0.3f;
    float det = a*c - bq*bq;
    float inv_det = 1.0f / fmaxf(det, 1e-12f);
    float cA = c*inv_det, cB = -bq*inv_det, cC = a*inv_det;
    float mid = 0.5f*(a + c);
    float lam1 = mid + sqrtf(fmaxf(mid*mid - det, 0.1f));
    radii_out[i] = ceilf(3.0f * sqrtf(lam1));
    float mx = fx*pxv/zc + 0.5f*W_IMG - 0.5f;
    float my = fy*pyv/zc + 0.5f*H_IMG - 0.5f;
    bool valid = (zg > 0.2f) && (det > 0.0f);
    float op = opac[i];
    float sthr = 2.0f * logf(255.0f * op);
    float4 bb = make_float4(1e30f, -1e30f, 1e30f, -1e30f);
    if (valid && sthr > 0.0f) {
        float hx = sqrtf(sthr * a) * 1.001f + 0.6f;
        float hy = sqrtf(sthr * c) * 1.001f + 0.6f;
        bb = make_float4(mx - hx, mx + hx, my - hy, my + hy);
    }
    g_bbv[i]  = bb;
    g_p1v[i]  = make_float4(mx, my, cA, cB);
    g_p2v[i]  = make_float4(cC, op, zg, 0.0f);
    g_clv[i]  = make_float4(colors[3*i], colors[3*i+1], colors[3*i+2], 0.0f);
    g_keyv[i] = ((unsigned long long)__float_as_uint(zg) << 32) | (unsigned)i;
}

__global__ __launch_bounds__(256) void gs_raster(
    const float* __restrict__ bg, float* __restrict__ out, int n)
{
    __shared__ float4 sP1[MAXG + 4];
    __shared__ float4 sP2[MAXG + 4];
    __shared__ float4 sCl[MAXG + 4];
    __shared__ unsigned long long sKey[MAXG];
    __shared__ int sK;

    const int tid  = threadIdx.x;
    const int lane = tid & 31;
    const int seg = tid & 3;
    const int p   = tid >> 2;                     // 0..63
    const int px  = blockIdx.x * TILE + (p & (TILE - 1));
    const int py  = blockIdx.y * TILE + (p / TILE);
    const float tX0 = (float)(blockIdx.x * TILE), tX1 = tX0 + (TILE - 1);
    const float tY0 = (float)(blockIdx.y * TILE), tY1 = tY0 + (TILE - 1);

    if (tid == 0) sK = 0;
    __syncthreads();

    // Phase A: bbox cull, warp-aggregated unordered compaction (rank fixes order)
    #pragma unroll
    for (int base = 0; base < MAXG; base += 256) {
        int g = base + tid;
        bool pred = false;
        if (g < n) {
            float4 bb = g_bbv[g];
            pred = (bb.x <= tX1) && (bb.y >= tX0) && (bb.z <= tY1) && (bb.w >= tY0);
        }
        unsigned msk = __ballot_sync(0xffffffffu, pred);
        int nset = __popc(msk);
        int base_s = 0;
        if (lane == 0 && nset) base_s = atomicAdd(&sK, nset);
        base_s = __shfl_sync(0xffffffffu, base_s, 0);
        if (pred) {
            int off = __popc(msk & ((1u << lane) - 1u));
            sKey[base_s + off] = g_keyv[g];
        }
    }
    __syncthreads();

    // Phase B: stable rank via unique u64 keys; LDG prefetch overlaps rank loop
    const int k = sK;
    for (int e = tid; e < k; e += 256) {
        unsigned long long key = sKey[e];
        int ie = (int)(unsigned)(key & 0xffffffffu);
        float4 a = g_p1v[ie];           // independent LDGs issue before rank loop
        float4 b = g_p2v[ie];
        float4 c = g_clv[ie];
        int r = 0;
        #pragma unroll 4
        for (int j = 0; j < k; j++) r += (sKey[j] < key) ? 1 : 0;
        sP1[r] = a; sP2[r] = b; sCl[r] = c;
    }
    if (tid < 3) {
        float4 z4 = make_float4(0.f, 0.f, 0.f, 0.f);
        sP1[k + tid] = z4; sP2[k + tid] = z4; sCl[k + tid] = z4;
    }
    __syncthreads();

    // Phase C: 4-way segmented compositing
    const float fpx = (float)px, fpy = (float)py;
    float T = 1.0f, aR = 0.f, aG = 0.f, aB = 0.f, dep = 0.f, mw = 0.f;
    int cnt = 0;
    const int q = (k + 3) >> 2;
    const int s0 = seg * q;
    #pragma unroll 2
    for (int j = 0; j < q; j++) {
        int idx = s0 + j;
        float4 p1 = sP1[idx];
        float4 p2 = sP2[idx];
        float dx = fpx - p1.x, dy = fpy - p1.y;
        float pw = -0.5f * (p1.z * dx * dx + p2.x * dy * dy) - p1.w * dx * dy;
        float al = fminf(0.99f, p2.y * __expf(fminf(pw, 0.0f)));
        bool kp = (pw <= 0.0f) && (al >= ALPHA_MIN);
        float a_eff = kp ? al : 0.0f;
        float4 c4 = sCl[idx];
        float wv = a_eff * T;
        aR = fmaf(wv, c4.x, aR);
        aG = fmaf(wv, c4.y, aG);
        aB = fmaf(wv, c4.z, aB);
        dep = fmaf(wv, p2.z, dep);
        mw = fmaxf(mw, wv);
        cnt += kp ? 1 : 0;
        T *= (1.0f - a_eff);
    }

    // merge 4 segment states (adjacent lanes)
    #pragma unroll
    for (int d = 1; d <= 2; d <<= 1) {
        float To = __shfl_xor_sync(0xffffffffu, T,  d);
        float ro = __shfl_xor_sync(0xffffffffu, aR, d);
        float go = __shfl_xor_sync(0xffffffffu, aG, d);
        float bo = __shfl_xor_sync(0xffffffffu, aB, d);
        float do_ = __shfl_xor_sync(0xffffffffu, dep, d);
        float mo = __shfl_xor_sync(0xffffffffu, mw, d);
        int   co = __shfl_xor_sync(0xffffffffu, cnt, d);
        bool rightSelf = (lane & d) != 0;
        float TL = rightSelf ? To : T,   TR = rightSelf ? T   : To;
        float rL = rightSelf ? ro : aR,  rR = rightSelf ? aR  : ro;
        float gL = rightSelf ? go : aG,  gR = rightSelf ? aG  : go;
        float bL = rightSelf ? bo : aB,  bR = rightSelf ? aB  : bo;
        float dL = rightSelf ? do_ : dep, dR = rightSelf ? dep : do_;
        float mL = rightSelf ? mo : mw,  mR = rightSelf ? mw  : mo;
        aR  = fmaf(TL, rR, rL);
        aG  = fmaf(TL, gR, gL);
        aB  = fmaf(TL, bR, bL);
        dep = fmaf(TL, dR, dL);
        mw  = fmaxf(mL, TL * mR);
        T   = TL * TR;
        cnt += co;
    }

    if (seg == 0) {
        const int HW = H_IMG * W_IMG;
        const int pix = py * W_IMG + px;
        out[3 * pix + 0] = aR + T * bg[0];
        out[3 * pix + 1] = aG + T * bg[1];
        out[3 * pix + 2] = aB + T * bg[2];
        float* o2 = out + 3 * HW + n;
        o2[pix]          = (float)cnt;   // out_observe
        o2[HW + pix]     = dep;          // out_plane_depth
        o2[2 * HW + pix] = mw;           // app_opacity
        o2[3 * HW + pix] = 1.0f - T;     // color_alpha
    }
}

extern "C" void kernel_launch(void* const* d_in, const int* in_sizes, int n_in,
                              void* d_out, int out_size) {
    const float* means  = (const float*)d_in[0];
    const float* opac   = (const float*)d_in[1];
    const float* colors = (const float*)d_in[2];
    const float* scales = (const float*)d_in[3];
    const float* rots   = (const float*)d_in[4];
    const float* bg     = (const float*)d_in[5];
    const float* vm     = (const float*)d_in[6];
    const int n = in_sizes[0] / 3;
    float* out = (float*)d_out;

    gs_pre<<<(n + 255) / 256, 256>>>(means, opac, colors, scales, rots, vm,
                                     out + (size_t)3 * H_IMG * W_IMG, n);
    dim3 grid(W_IMG / TILE, H_IMG / TILE);
    gs_raster<<<grid, 256>>>(bg, out, n);
}

// round 6
// speedup vs baseline: 1.1037x; 1.1037x over previous
#include <cuda_runtime.h>
#include <math.h>

#define H_IMG 256
#define W_IMG 256
#define TILE 8
#define TANFOV 0.7f
#define ALPHA_MIN (1.0f/255.0f)
#define MAXG 512

__device__ float4 g_p1v[MAXG];               // mx, my, conicA, conicB
__device__ float4 g_p2v[MAXG];               // conicC, opacity, z, negln
__device__ float4 g_clv[MAXG];               // r, g, b, 0
__device__ unsigned g_trv[MAXG];             // packed tile range x0|x1<<8|y0<<16|y1<<24
__device__ unsigned long long g_keyv[MAXG];  // (float_bits(z)<<32) | idx

// exp(x) via 2^y, deg-5 kernel. rel err ~2e-6 on f in [-0.5,0.5]. FMA/ALU only.
__device__ __forceinline__ float exp_fma(float x) {
    float y = x * 1.44269504088896f;
    float t = y + 12582912.0f;                 // round-to-nearest int
    float nf = t - 12582912.0f;
    float f = y - nf;
    int ni = __float_as_int(t) - 0x4B400000;   // exact integer n
    float p = 1.33335581e-3f;
    p = fmaf(p, f, 9.61812911e-3f);
    p = fmaf(p, f, 5.55041087e-2f);
    p = fmaf(p, f, 2.40226507e-1f);
    p = fmaf(p, f, 6.93147180e-1f);
    p = fmaf(p, f, 1.0f);
    float s = __int_as_float((ni << 23) + 0x3F800000);
    return p * s;
}

__global__ __launch_bounds__(64) void gs_pre(
    const float* __restrict__ means,
    const float* __restrict__ opac,
    const float* __restrict__ colors,
    const float* __restrict__ scales,
    const float* __restrict__ rots,
    const float* __restrict__ vm,
    float* __restrict__ radii_out, int n)
{
    const int i = blockIdx.x * 64 + threadIdx.x;
    if (i >= n) return;

    const float fx = W_IMG / (2.0f * TANFOV);
    const float fy = H_IMG / (2.0f * TANFOV);
    const float R00 = vm[0], R01 = vm[1], R02 = vm[2],  t0 = vm[3];
    const float R10 = vm[4], R11 = vm[5], R12 = vm[6],  t1 = vm[7];
    const float R20 = vm[8], R21 = vm[9], R22 = vm[10], t2 = vm[11];

    float m0 = means[3*i], m1 = means[3*i+1], m2 = means[3*i+2];
    float pxv = R00*m0 + R01*m1 + R02*m2 + t0;
    float pyv = R10*m0 + R11*m1 + R12*m2 + t1;
    float zg  = R20*m0 + R21*m1 + R22*m2 + t2;
    float zc = fmaxf(zg, 1e-4f);
    float lim = 1.3f * TANFOV;
    float txc = fminf(fmaxf(pxv/zc, -lim), lim) * zc;
    float tyc = fminf(fmaxf(pyv/zc, -lim), lim) * zc;

    float q0 = rots[4*i], q1 = rots[4*i+1], q2 = rots[4*i+2], q3 = rots[4*i+3];
    float qn = rsqrtf(q0*q0 + q1*q1 + q2*q2 + q3*q3);
    q0 *= qn; q1 *= qn; q2 *= qn; q3 *= qn;
    float xx = q1*q1, yy = q2*q2, zz = q3*q3;
    float xy = q1*q2, xz = q1*q3, yz = q2*q3;
    float rx = q0*q1, ry = q0*q2, rz = q0*q3;
    float Q00 = 1.f-2.f*(yy+zz), Q01 = 2.f*(xy-rz),     Q02 = 2.f*(xz+ry);
    float Q10 = 2.f*(xy+rz),     Q11 = 1.f-2.f*(xx+zz), Q12 = 2.f*(yz-rx);
    float Q20 = 2.f*(xz-ry),     Q21 = 2.f*(yz+rx),     Q22 = 1.f-2.f*(xx+yy);
    float sx = scales[3*i], sy = scales[3*i+1], sz2 = scales[3*i+2];
    float M00 = Q00*sx, M01 = Q01*sy, M02 = Q02*sz2;
    float M10 = Q10*sx, M11 = Q11*sy, M12 = Q12*sz2;
    float M20 = Q20*sx, M21 = Q21*sy, M22 = Q22*sz2;
    float C00 = M00*M00 + M01*M01 + M02*M02;
    float C01 = M00*M10 + M01*M11 + M02*M12;
    float C02 = M00*M20 + M01*M21 + M02*M22;
    float C11 = M10*M10 + M11*M11 + M12*M12;
    float C12 = M10*M20 + M11*M21 + M12*M22;
    float C22 = M20*M20 + M21*M21 + M22*M22;
    float j00 = fx/zc, j02 = -fx*txc/(zc*zc);
    float j11 = fy/zc, j12 = -fy*tyc/(zc*zc);
    float T00 = j00*R00 + j02*R20, T01 = j00*R01 + j02*R21, T02 = j00*R02 + j02*R22;
    float T10 = j11*R10 + j12*R20, T11 = j11*R11 + j12*R21, T12 = j11*R12 + j12*R22;
    float u0 = C00*T00 + C01*T01 + C02*T02;
    float u1 = C01*T00 + C11*T01 + C12*T02;
    float u2 = C02*T00 + C12*T01 + C22*T02;
    float v0 = C00*T10 + C01*T11 + C02*T12;
    float v1 = C01*T10 + C11*T11 + C12*T12;
    float v2 = C02*T10 + C12*T11 + C22*T12;
    float a  = T00*u0 + T01*u1 + T02*u2 + 0.3f;
    float bq = T10*u0 + T11*u1 + T12*u2;
    float c  = T10*v0 + T11*v1 + T12*v2 + 0.3f;
    float det = a*c - bq*bq;
    float inv_det = 1.0f / fmaxf(det, 1e-12f);
    float cA = c*inv_det, cB = -bq*inv_det, cC = a*inv_det;
    float mid = 0.5f*(a + c);
    float lam1 = mid + sqrtf(fmaxf(mid*mid - det, 0.1f));
    radii_out[i] = ceilf(3.0f * sqrtf(lam1));
    float mx = fx*pxv/zc + 0.5f*W_IMG - 0.5f;
    float my = fy*pyv/zc + 0.5f*H_IMG - 0.5f;
    bool valid = (zg > 0.2f) && (det > 0.0f);
    float op = opac[i];
    float sthr = 2.0f * logf(255.0f * op);

    unsigned tr = 0x000000FFu;  // x0=255 > x1=0 : empty
    if (valid && sthr > 0.0f) {
        float hx = sqrtf(sthr * a) * 1.001f + 0.6f;
        float hy = sqrtf(sthr * c) * 1.001f + 0.6f;
        float x0f = fminf(fmaxf(floorf((mx - hx) * 0.125f), 0.f), 31.f);
        float x1f = fminf(fmaxf(floorf((mx + hx) * 0.125f), 0.f), 31.f);
        float y0f = fminf(fmaxf(floorf((my - hy) * 0.125f), 0.f), 31.f);
        float y1f = fminf(fmaxf(floorf((my + hy) * 0.125f), 0.f), 31.f);
        bool nonempty = (mx + hx >= 0.f) && (mx - hx <= 255.f) &&
                        (my + hy >= 0.f) && (my - hy <= 255.f);
        if (nonempty)
            tr = (unsigned)x0f | ((unsigned)x1f << 8) |
                 ((unsigned)y0f << 16) | ((unsigned)y1f << 24);
    }
    g_trv[i]  = tr;
    g_p1v[i]  = make_float4(mx, my, cA, cB);
    g_p2v[i]  = make_float4(cC, op, zg, -logf(255.0f * op));
    g_clv[i]  = make_float4(colors[3*i], colors[3*i+1], colors[3*i+2], 0.0f);
    g_keyv[i] = ((unsigned long long)__float_as_uint(zg) << 32) | (unsigned)i;
}

__global__ __launch_bounds__(256) void gs_raster(
    const float* __restrict__ bg, float* __restrict__ out, int n)
{
    __shared__ float4 sP1[MAXG + 4];
    __shared__ float4 sP2[MAXG + 4];
    __shared__ float4 sCl[MAXG + 4];
    __shared__ unsigned long long sKey[MAXG];
    __shared__ int sK;

    const int tid  = threadIdx.x;
    const int lane = tid & 31;
    const int seg = tid & 3;
    const int p   = tid >> 2;                     // 0..63

    // center-first tile remap: heavy central tiles get scheduled first
    const int bid = blockIdx.x;
    int iy = bid >> 5, ix = bid & 31;
    int bx = (ix & 1) ? (16 + (ix >> 1)) : (15 - (ix >> 1));
    int by = (iy & 1) ? (16 + (iy >> 1)) : (15 - (iy >> 1));

    const int px = bx * TILE + (p & (TILE - 1));
    const int py = by * TILE + (p / TILE);
    const float bgr = bg[0], bgg = bg[1], bgb = bg[2];

    if (tid == 0) sK = 0;
    __syncthreads();

    // Phase A: int tile-range cull, warp-aggregated unordered compaction
    #pragma unroll
    for (int base = 0; base < MAXG; base += 256) {
        int g = base + tid;
        bool pred = false;
        if (g < n) {
            unsigned tr = g_trv[g];
            int x0 = tr & 255, x1 = (tr >> 8) & 255;
            int y0 = (tr >> 16) & 255, y1 = tr >> 24;
            pred = (bx >= x0) && (bx <= x1) && (by >= y0) && (by <= y1);
        }
        unsigned msk = __ballot_sync(0xffffffffu, pred);
        int nset = __popc(msk);
        int base_s = 0;
        if (lane == 0 && nset) base_s = atomicAdd(&sK, nset);
        base_s = __shfl_sync(0xffffffffu, base_s, 0);
        if (pred) {
            int off = __popc(msk & ((1u << lane) - 1u));
            sKey[base_s + off] = g_keyv[g];
        }
    }
    __syncthreads();

    const int k = sK;
    const int HW = H_IMG * W_IMG;
    const int pix = py * W_IMG + px;

    if (k == 0) {                       // empty tile fast path
        if (seg == 0) {
            out[3 * pix + 0] = bgr;
            out[3 * pix + 1] = bgg;
            out[3 * pix + 2] = bgb;
            float* o2 = out + 3 * HW + n;
            o2[pix] = 0.0f; o2[HW + pix] = 0.0f;
            o2[2 * HW + pix] = 0.0f; o2[3 * HW + pix] = 0.0f;
        }
        return;
    }

    // Phase B: stable rank via unique u64 keys; LDG prefetch overlaps rank loop
    for (int e = tid; e < k; e += 256) {
        unsigned long long key = sKey[e];
        int ie = (int)(unsigned)(key & 0xffffffffu);
        float4 a = g_p1v[ie];
        float4 b = g_p2v[ie];
        float4 c = g_clv[ie];
        int r = 0;
        #pragma unroll 4
        for (int j = 0; j < k; j++) r += (sKey[j] < key) ? 1 : 0;
        sP1[r] = a; sP2[r] = b; sCl[r] = c;
    }
    if (tid < 3) {
        // padding record: conic=0 -> pw=0; negln=1 -> keep=false
        sP1[k + tid] = make_float4(0.f, 0.f, 0.f, 0.f);
        sP2[k + tid] = make_float4(0.f, 0.f, 0.f, 1.0f);
        sCl[k + tid] = make_float4(0.f, 0.f, 0.f, 0.f);
    }
    __syncthreads();

    // Phase C: 4-way segmented compositing, MUFU-free
    const float fpx = (float)px, fpy = (float)py;
    float T = 1.0f, aR = 0.f, aG = 0.f, aB = 0.f, dep = 0.f, mw = 0.f;
    int cnt = 0;
    const int q = (k + 3) >> 2;
    const int s0 = seg * q;
    #pragma unroll 2
    for (int j = 0; j < q; j++) {
        int idx = s0 + j;
        float4 p1 = sP1[idx];
        float4 p2 = sP2[idx];
        float dx = fpx - p1.x, dy = fpy - p1.y;
        float pw = -0.5f * (p1.z * dx * dx + p2.x * dy * dy) - p1.w * dx * dy;
        bool kp = (pw <= 0.0f) && (pw >= p2.w);    // alpha>=1/255 test, exp-free
        float al = fminf(0.99f, p2.y * exp_fma(fmaxf(pw, -16.0f)));
        float a_eff = kp ? al : 0.0f;
        float4 c4 = sCl[idx];
        float wv = a_eff * T;
        aR = fmaf(wv, c4.x, aR);
        aG = fmaf(wv, c4.y, aG);
        aB = fmaf(wv, c4.z, aB);
        dep = fmaf(wv, p2.z, dep);
        mw = fmaxf(mw, wv);
        cnt += kp ? 1 : 0;
        T *= (1.0f - a_eff);
    }

    // merge 4 segment states (adjacent lanes)
    #pragma unroll
    for (int d = 1; d <= 2; d <<= 1) {
        float To = __shfl_xor_sync(0xffffffffu, T,  d);
        float ro = __shfl_xor_sync(0xffffffffu, aR, d);
        float go = __shfl_xor_sync(0xffffffffu, aG, d);
        float bo = __shfl_xor_sync(0xffffffffu, aB, d);
        float do_ = __shfl_xor_sync(0xffffffffu, dep, d);
        float mo = __shfl_xor_sync(0xffffffffu, mw, d);
        int   co = __shfl_xor_sync(0xffffffffu, cnt, d);
        bool rightSelf = (lane & d) != 0;
        float TL = rightSelf ? To : T,   TR = rightSelf ? T   : To;
        float rL = rightSelf ? ro : aR,  rR = rightSelf ? aR  : ro;
        float gL = rightSelf ? go : aG,  gR = rightSelf ? aG  : go;
        float bL = rightSelf ? bo : aB,  bR = rightSelf ? aB  : bo;
        float dL = rightSelf ? do_ : dep, dR = rightSelf ? dep : do_;
        float mL = rightSelf ? mo : mw,  mR = rightSelf ? mw  : mo;
        aR  = fmaf(TL, rR, rL);
        aG  = fmaf(TL, gR, gL);
        aB  = fmaf(TL, bR, bL);
        dep = fmaf(TL, dR, dL);
        mw  = fmaxf(mL, TL * mR);
        T   = TL * TR;
        cnt += co;
    }

    if (seg == 0) {
        out[3 * pix + 0] = aR + T * bgr;
        out[3 * pix + 1] = aG + T * bgg;
        out[3 * pix + 2] = aB + T * bgb;
        float* o2 = out + 3 * HW + n;
        o2[pix]          = (float)cnt;   // out_observe
        o2[HW + pix]     = dep;          // out_plane_depth
        o2[2 * HW + pix] = mw;           // app_opacity
        o2[3 * HW + pix] = 1.0f - T;     // color_alpha
    }
}

extern "C" void kernel_launch(void* const* d_in, const int* in_sizes, int n_in,
                              void* d_out, int out_size) {
    const float* means  = (const float*)d_in[0];
    const float* opac   = (const float*)d_in[1];
    const float* colors = (const float*)d_in[2];
    const float* scales = (const float*)d_in[3];
    const float* rots   = (const float*)d_in[4];
    const float* bg     = (const float*)d_in[5];
    const float* vm     = (const float*)d_in[6];
    const int n = in_sizes[0] / 3;
    float* out = (float*)d_out;

    gs_pre<<<(n + 63) / 64, 64>>>(means, opac, colors, scales, rots, vm,
                                  out + (size_t)3 * H_IMG * W_IMG, n);
    gs_raster<<<(W_IMG / TILE) * (H_IMG / TILE), 256>>>(bg, out, n);
}